// round 16
// baseline (speedup 1.0000x reference)
#include <cuda_runtime.h>
#include <cuda_fp16.h>
#include <stdint.h>

// ---------------------------------------------------------------------------
// HashEncoder (Instant-NGP multires hash grid): B=2097152 pts, D=3, L=16, C=2
// base_res=16, desired=2048, log2_hashmap=19.
//
// res : 16 23 31 43 59 | 81 112 154 213 295 407 562 777 1073 1483 2048
// l<5 dense (res^3 aligned to 8), l>=5 hashed with hmap = 2^19.
//
// R14: measured fact (R13): scattered LDG.128 = 1 wavefront/lane, same as 4B.
// Hash levels: unconditional 16B load at ia&~3 covers entries {ia&~3..+3};
// since ia^ib = x0^x1, pairs with d<4 (75%: d=1 50%, d=3 25%, d=0 clamp) have
// BOTH corners in that one load. Only d>=4 (25%) issues a second (4B) load.
// Hash loads/level: 6 -> 5 with zero extra table footprint.
// Dense levels: clamp-baked quad table, 2 x LDG.128 per level (R13, proven).
// Lane-loads/point: 76 -> 65.
// ---------------------------------------------------------------------------

#define NLEV 16
#define BLOCK 256
#define PTS_PER_BLK 32            // 8 threads per point, 2 levels per thread
#define TOTAL_PARAMS 6098120
#define DENSE_PARAMS 330952       // OFFSETS[5]
#define HASH_PARAMS (TOTAL_PARAMS - DENSE_PARAMS)   // 11 * 2^19

__constant__ uint32_t c_res[NLEV] = {
    16u, 23u, 31u, 43u, 59u, 81u, 112u, 154u,
    213u, 295u, 407u, 562u, 777u, 1073u, 1483u, 2048u
};
__constant__ uint32_t c_off[NLEV] = {
    0u, 4096u, 16264u, 46056u, 125568u, 330952u, 855240u, 1379528u,
    1903816u, 2428104u, 2952392u, 3476680u, 4000968u, 4525256u, 5049544u, 5573832u
};

__device__ float g_scales[NLEV];
// fp16x2 shadow (one uint32 per entry); only the hash region is read.
// Hash level bases (330952 + k*2^19) are all multiples of 4 -> 16B-aligned.
__device__ __align__(128) uint32_t g_half[TOTAL_PARAMS];
// Dense quad table: per entry the 4 (x,y)-corner values of its cell, clamped.
__device__ __align__(128) uint4 g_quad[DENSE_PARAMS];

__device__ __forceinline__ uint32_t f2h(float2 e) {
    __half2 h = __floats2half2_rn(e.x, e.y);
    return *(uint32_t*)&h;
}

// One setup kernel: scales + dense quad + hash-region fp16 shadow.
__global__ __launch_bounds__(256)
void setup_kernel(const float2* __restrict__ emb) {
    if (blockIdx.x == 0 && threadIdx.x < NLEV) {
        double s = exp2((double)threadIdx.x * (7.0 / 15.0)) * 16.0 - 1.0;
        g_scales[threadIdx.x] = (float)s;
    }
    const int gi = blockIdx.x * blockDim.x + threadIdx.x;

    // Dense quad: decompose gi -> (level, x, y); bake x/y clamping.
    if (gi < DENSE_PARAMS) {
        int l = 0;
        #pragma unroll
        for (int k = 1; k < 5; ++k)
            if ((uint32_t)gi >= c_off[k]) l = k;
        const uint32_t res = c_res[l];
        const uint32_t off = c_off[l];
        const uint32_t li  = (uint32_t)gi - off;
        const uint32_t r2  = res * res;
        if (li < r2 * res) {                      // skip align-to-8 padding
            const uint32_t x = li % res;
            const uint32_t rem = li / res;
            const uint32_t y = rem % res;
            const uint32_t x1 = min(x + 1u, res - 1u);
            const uint32_t y1 = min(y + 1u, res - 1u);
            const uint32_t b  = (uint32_t)gi - x - y * res;  // (0,0) of plane row
            uint4 q;
            q.x = f2h(emb[b + x  + y  * res]);
            q.y = f2h(emb[b + x1 + y  * res]);
            q.z = f2h(emb[b + x  + y1 * res]);
            q.w = f2h(emb[b + x1 + y1 * res]);
            g_quad[gi] = q;
        } else {
            g_quad[gi] = make_uint4(0u, 0u, 0u, 0u);
        }
    }
    // Hash region fp16 shadow: pair i covers entries DENSE_PARAMS+2i, +2i+1.
    if (gi < HASH_PARAMS / 2) {
        const int base = DENSE_PARAMS + 2 * gi;
        const float4 e = *(const float4*)(emb + base);
        const uint32_t w0 = f2h(make_float2(e.x, e.y));
        const uint32_t w1 = f2h(make_float2(e.z, e.w));
        *(uint64_t*)&g_half[base] = ((uint64_t)w1 << 32) | w0;
    }
}

// Hash-level pair-gather v2: one unconditional aligned 16B load at a&~3
// covers both corners when (a^b) < 4 (75% incl. clamp d=0); otherwise a
// predicated 4B load fetches b. Static 2-level selects (no dynamic reg
// indexing -> no spills).
__device__ __forceinline__ void pair_gather4(const uint32_t* __restrict__ tabh,
                                             uint32_t a, uint32_t b,
                                             float2& ea, float2& eb)
{
    const uint32_t d = a ^ b;
    const unsigned need2 = (d >= 4u) ? 1u : 0u;
    const uint32_t* p4 = tabh + (a & ~3u);   // 16B-aligned
    const uint32_t* pb = tabh + b;
    uint32_t v0, v1, v2, v3, ub;
    asm volatile(
        "{\n\t"
        ".reg .pred p;\n\t"
        "setp.ne.u32 p, %5, 0;\n\t"
        "mov.u32 %4, 0;\n\t"
        "ld.global.nc.v4.u32 {%0,%1,%2,%3}, [%6];\n\t"
        "@p ld.global.nc.u32 %4, [%7];\n\t"
        "}"
        : "=r"(v0), "=r"(v1), "=r"(v2), "=r"(v3), "=r"(ub)
        : "r"(need2), "l"(p4), "l"(pb));
    const uint32_t wa  = (a & 2u) ? ((a & 1u) ? v3 : v2)
                                  : ((a & 1u) ? v1 : v0);
    const uint32_t wbi = (b & 2u) ? ((b & 1u) ? v3 : v2)
                                  : ((b & 1u) ? v1 : v0);
    const uint32_t wb  = need2 ? ub : wbi;
    ea = __half22float2(*(const __half2*)&wa);
    eb = __half22float2(*(const __half2*)&wb);
}

__global__ __launch_bounds__(BLOCK, 7)
void hash_encode_kernel(const float* __restrict__ inputs,
                        float4* __restrict__ out,
                        int npts)
{
    __shared__ float s_in[PTS_PER_BLK * 3];
    __shared__ float s_scale[NLEV];

    const int tid = threadIdx.x;
    {
        int gidx = blockIdx.x * (PTS_PER_BLK * 3) + tid;
        if (tid < PTS_PER_BLK * 3 && gidx < npts * 3)
            s_in[tid] = inputs[gidx];
        if (tid < NLEV)
            s_scale[tid] = g_scales[tid];
    }
    __syncthreads();

    const int p = tid >> 3;       // point within block (0..31)
    const int s = tid & 7;        // sub-thread: handles levels 2s, 2s+1
    const long long point = (long long)blockIdx.x * PTS_PER_BLK + p;
    if (point >= npts) return;

    const float x = s_in[p * 3 + 0];
    const float y = s_in[p * 3 + 1];
    const float z = s_in[p * 3 + 2];

    float4 r;

    #pragma unroll
    for (int i = 0; i < 2; ++i) {
        const int l = (s << 1) + i;
        const float scale  = s_scale[l];
        const uint32_t res = c_res[l];

        // pos = x*scale + 0.5, NO fma contraction (floor must match reference).
        const float posx = __fadd_rn(__fmul_rn(x, scale), 0.5f);
        const float posy = __fadd_rn(__fmul_rn(y, scale), 0.5f);
        const float posz = __fadd_rn(__fmul_rn(z, scale), 0.5f);
        const float fx = floorf(posx), fy = floorf(posy), fz = floorf(posz);
        const float tx = posx - fx,  ty = posy - fy,  tz = posz - fz;
        const uint32_t gx = (uint32_t)fx, gy = (uint32_t)fy, gz = (uint32_t)fz;
        const uint32_t rm1 = res - 1u;
        const uint32_t x0 = min(gx,      rm1), x1 = min(gx + 1u, rm1);
        const uint32_t y0 = min(gy,      rm1), y1 = min(gy + 1u, rm1);
        const uint32_t z0 = min(gz,      rm1), z1 = min(gz + 1u, rm1);

        const float wx0 = 1.0f - tx, wy0 = 1.0f - ty, wz0 = 1.0f - tz;
        float a0 = 0.0f, a1 = 0.0f;

        if (l >= 5) {
            const uint32_t* __restrict__ tabh = g_half + c_off[l];
            const uint32_t hy0 = y0 * 2654435761u, hy1 = y1 * 2654435761u;
            const uint32_t hz0 = z0 * 805459861u,  hz1 = z1 * 805459861u;
            const uint32_t m = 0x7FFFFu;
            uint32_t ia[4], ib[4];
            ia[0] = (x0 ^ hy0 ^ hz0) & m;  ib[0] = (x1 ^ hy0 ^ hz0) & m;
            ia[1] = (x0 ^ hy1 ^ hz0) & m;  ib[1] = (x1 ^ hy1 ^ hz0) & m;
            ia[2] = (x0 ^ hy0 ^ hz1) & m;  ib[2] = (x1 ^ hy0 ^ hz1) & m;
            ia[3] = (x0 ^ hy1 ^ hz1) & m;  ib[3] = (x1 ^ hy1 ^ hz1) & m;
            float2 ea[4], eb[4];
            #pragma unroll
            for (int q = 0; q < 4; ++q)
                pair_gather4(tabh, ia[q], ib[q], ea[q], eb[q]);
            #pragma unroll
            for (int q = 0; q < 4; ++q) {
                const float wy = (q & 1) ? ty : wy0;
                const float wz = (q & 2) ? tz : wz0;
                const float wyz = __fmul_rn(wy, wz);
                const float wa  = __fmul_rn(wx0, wyz);
                const float wb  = __fmul_rn(tx,  wyz);
                a0 = fmaf(wa, ea[q].x, a0);
                a1 = fmaf(wa, ea[q].y, a1);
                a0 = fmaf(wb, eb[q].x, a0);
                a1 = fmaf(wb, eb[q].y, a1);
            }
        } else {
            // Dense quad: one LDG.128 per z-plane; clamping baked at build.
            const uint4* __restrict__ quad = g_quad + c_off[l];
            const uint32_t r2 = res * res;
            const uint32_t base = x0 + y0 * res;
            const uint4 v0 = __ldg(quad + base + z0 * r2);
            const uint4 v1 = __ldg(quad + base + z1 * r2);
            const float2 e00a = __half22float2(*(const __half2*)&v0.x);
            const float2 e10a = __half22float2(*(const __half2*)&v0.y);
            const float2 e01a = __half22float2(*(const __half2*)&v0.z);
            const float2 e11a = __half22float2(*(const __half2*)&v0.w);
            const float2 e00b = __half22float2(*(const __half2*)&v1.x);
            const float2 e10b = __half22float2(*(const __half2*)&v1.y);
            const float2 e01b = __half22float2(*(const __half2*)&v1.z);
            const float2 e11b = __half22float2(*(const __half2*)&v1.w);
            const float w00a = __fmul_rn(__fmul_rn(wx0, wy0), wz0);
            const float w10a = __fmul_rn(__fmul_rn(tx,  wy0), wz0);
            const float w01a = __fmul_rn(__fmul_rn(wx0, ty),  wz0);
            const float w11a = __fmul_rn(__fmul_rn(tx,  ty),  wz0);
            const float w00b = __fmul_rn(__fmul_rn(wx0, wy0), tz);
            const float w10b = __fmul_rn(__fmul_rn(tx,  wy0), tz);
            const float w01b = __fmul_rn(__fmul_rn(wx0, ty),  tz);
            const float w11b = __fmul_rn(__fmul_rn(tx,  ty),  tz);
            a0 = fmaf(w00a, e00a.x, a0);  a1 = fmaf(w00a, e00a.y, a1);
            a0 = fmaf(w10a, e10a.x, a0);  a1 = fmaf(w10a, e10a.y, a1);
            a0 = fmaf(w01a, e01a.x, a0);  a1 = fmaf(w01a, e01a.y, a1);
            a0 = fmaf(w11a, e11a.x, a0);  a1 = fmaf(w11a, e11a.y, a1);
            a0 = fmaf(w00b, e00b.x, a0);  a1 = fmaf(w00b, e00b.y, a1);
            a0 = fmaf(w10b, e10b.x, a0);  a1 = fmaf(w10b, e10b.y, a1);
            a0 = fmaf(w01b, e01b.x, a0);  a1 = fmaf(w01b, e01b.y, a1);
            a0 = fmaf(w11b, e11b.x, a0);  a1 = fmaf(w11b, e11b.y, a1);
        }
        if (i == 0) { r.x = a0; r.y = a1; }
        else        { r.z = a0; r.w = a1; }
    }

    // Warp = 4 points x 8 subthreads -> 512B contiguous store, fully coalesced.
    out[point * 8 + s] = r;
}

extern "C" void kernel_launch(void* const* d_in, const int* in_sizes, int n_in,
                              void* d_out, int out_size)
{
    const float*  inputs = (const float*)d_in[0];
    const float2* emb    = (const float2*)d_in[1];
    float4*       out    = (float4*)d_out;

    const int npts = in_sizes[0] / 3;

    const int setup_n = (HASH_PARAMS / 2 > DENSE_PARAMS) ? HASH_PARAMS / 2
                                                         : DENSE_PARAMS;
    setup_kernel<<<(setup_n + 255) / 256, 256>>>(emb);

    const int total_threads = npts * 8;
    const int nblocks = (total_threads + BLOCK - 1) / BLOCK;
    hash_encode_kernel<<<nblocks, BLOCK>>>(inputs, out, npts);
}

// round 17
// speedup vs baseline: 1.0021x; 1.0021x over previous
#include <cuda_runtime.h>
#include <cuda_fp16.h>
#include <stdint.h>

// ---------------------------------------------------------------------------
// HashEncoder (Instant-NGP multires hash grid): B=2097152 pts, D=3, L=16, C=2
// base_res=16, desired=2048, log2_hashmap=19.
//
// res : 16 23 31 43 59 | 81 112 154 213 295 407 562 777 1073 1483 2048
// l<5 dense (res^3 aligned to 8), l>=5 hashed with hmap = 2^19.
//
// R15 hybrid gather (calibrated: 8B duo = 1 wf; 16B pure-miss ~ 1.25 wf;
// 4B = 1 wf). Hash pair d = ia^ib (always 0 or 2^k-1):
//   d<2  (50% + clamp) -> one aligned 8B duo at a&~1        (1 wf)
//   d==3 (25%)         -> one aligned 16B load at a&~3      (~1.25 wf)
//   d>=4 (25%)         -> two 4B loads                      (2 wf)
// Dense levels: clamp-baked quad table, 2 x LDG.128/level (proven R13).
// Effective wf/pt: ~76 -> ~68.
// ---------------------------------------------------------------------------

#define NLEV 16
#define BLOCK 256
#define PTS_PER_BLK 32            // 8 threads per point, 2 levels per thread
#define TOTAL_PARAMS 6098120
#define DENSE_PARAMS 330952       // OFFSETS[5]
#define HASH_PARAMS (TOTAL_PARAMS - DENSE_PARAMS)   // 11 * 2^19

__constant__ uint32_t c_res[NLEV] = {
    16u, 23u, 31u, 43u, 59u, 81u, 112u, 154u,
    213u, 295u, 407u, 562u, 777u, 1073u, 1483u, 2048u
};
__constant__ uint32_t c_off[NLEV] = {
    0u, 4096u, 16264u, 46056u, 125568u, 330952u, 855240u, 1379528u,
    1903816u, 2428104u, 2952392u, 3476680u, 4000968u, 4525256u, 5049544u, 5573832u
};

__device__ float g_scales[NLEV];
// fp16x2 shadow (one uint32 per entry); only the hash region is read.
// Hash level bases (330952 + k*2^19) are multiples of 4 -> 16B-aligned.
__device__ __align__(128) uint32_t g_half[TOTAL_PARAMS];
// Dense quad table: per entry the 4 (x,y)-corner values of its cell, clamped.
__device__ __align__(128) uint4 g_quad[DENSE_PARAMS];

__device__ __forceinline__ uint32_t f2h(float2 e) {
    __half2 h = __floats2half2_rn(e.x, e.y);
    return *(uint32_t*)&h;
}

// One setup kernel: scales + dense quad + hash-region fp16 shadow.
__global__ __launch_bounds__(256)
void setup_kernel(const float2* __restrict__ emb) {
    if (blockIdx.x == 0 && threadIdx.x < NLEV) {
        double s = exp2((double)threadIdx.x * (7.0 / 15.0)) * 16.0 - 1.0;
        g_scales[threadIdx.x] = (float)s;
    }
    const int gi = blockIdx.x * blockDim.x + threadIdx.x;

    // Dense quad: decompose gi -> (level, x, y); bake x/y clamping.
    if (gi < DENSE_PARAMS) {
        int l = 0;
        #pragma unroll
        for (int k = 1; k < 5; ++k)
            if ((uint32_t)gi >= c_off[k]) l = k;
        const uint32_t res = c_res[l];
        const uint32_t off = c_off[l];
        const uint32_t li  = (uint32_t)gi - off;
        const uint32_t r2  = res * res;
        if (li < r2 * res) {                      // skip align-to-8 padding
            const uint32_t x = li % res;
            const uint32_t rem = li / res;
            const uint32_t y = rem % res;
            const uint32_t x1 = min(x + 1u, res - 1u);
            const uint32_t y1 = min(y + 1u, res - 1u);
            const uint32_t b  = (uint32_t)gi - x - y * res;  // (0,0) of plane row
            uint4 q;
            q.x = f2h(emb[b + x  + y  * res]);
            q.y = f2h(emb[b + x1 + y  * res]);
            q.z = f2h(emb[b + x  + y1 * res]);
            q.w = f2h(emb[b + x1 + y1 * res]);
            g_quad[gi] = q;
        } else {
            g_quad[gi] = make_uint4(0u, 0u, 0u, 0u);
        }
    }
    // Hash region fp16 shadow: pair i covers entries DENSE_PARAMS+2i, +2i+1.
    if (gi < HASH_PARAMS / 2) {
        const int base = DENSE_PARAMS + 2 * gi;
        const float4 e = *(const float4*)(emb + base);
        const uint32_t w0 = f2h(make_float2(e.x, e.y));
        const uint32_t w1 = f2h(make_float2(e.z, e.w));
        *(uint64_t*)&g_half[base] = ((uint64_t)w1 << 32) | w0;
    }
}

// Hybrid hash pair-gather: d = a^b is 0 or 2^k-1.
//   d<2  -> one aligned 8B duo at a&~1 (covers a and b; handles clamp d=0)
//   d==3 -> one aligned 16B load at a&~3 (covers a and a^3)
//   d>=4 -> two 4B loads
// True predication; outputs pre-zeroed.
__device__ __forceinline__ void pair_gather13(const uint32_t* __restrict__ tabh,
                                              uint32_t a, uint32_t b,
                                              float2& ea, float2& eb)
{
    const uint32_t d = a ^ b;
    const uint32_t* pduo = tabh + (a & ~1u);   // 8B-aligned
    const uint32_t* p16  = tabh + (a & ~3u);   // 16B-aligned
    const uint32_t* pa   = tabh + a;
    const uint32_t* pb   = tabh + b;
    unsigned long long duo;
    uint32_t v0, v1, v2, v3, ua, ub;
    asm volatile(
        "{\n\t"
        ".reg .pred p1, p3, pn;\n\t"
        "setp.lt.u32 p1, %7, 2;\n\t"
        "setp.eq.u32 p3, %7, 3;\n\t"
        "setp.ge.u32 pn, %7, 4;\n\t"
        "mov.u64 %0, 0;\n\t"
        "mov.u32 %1, 0;\n\t"
        "mov.u32 %2, 0;\n\t"
        "mov.u32 %3, 0;\n\t"
        "mov.u32 %4, 0;\n\t"
        "mov.u32 %5, 0;\n\t"
        "mov.u32 %6, 0;\n\t"
        "@p1 ld.global.nc.u64 %0, [%8];\n\t"
        "@p3 ld.global.nc.v4.u32 {%1,%2,%3,%4}, [%9];\n\t"
        "@pn ld.global.nc.u32 %5, [%10];\n\t"
        "@pn ld.global.nc.u32 %6, [%11];\n\t"
        "}"
        : "=l"(duo), "=r"(v0), "=r"(v1), "=r"(v2), "=r"(v3),
          "=r"(ua), "=r"(ub)
        : "r"(d), "l"(pduo), "l"(p16), "l"(pa), "l"(pb));
    uint32_t wa, wb;
    if (d < 2u) {
        const uint32_t lo = (uint32_t)duo;          // entry a&~1
        const uint32_t hi = (uint32_t)(duo >> 32);  // entry a|1
        wa = (a & 1u) ? hi : lo;
        wb = (b & 1u) ? hi : lo;                    // d=0 -> same as wa
    } else if (d == 3u) {
        const uint32_t a3 = a & 3u;
        const uint32_t b3 = a3 ^ 3u;
        wa = (a3 & 2u) ? ((a3 & 1u) ? v3 : v2) : ((a3 & 1u) ? v1 : v0);
        wb = (b3 & 2u) ? ((b3 & 1u) ? v3 : v2) : ((b3 & 1u) ? v1 : v0);
    } else {
        wa = ua;
        wb = ub;
    }
    ea = __half22float2(*(const __half2*)&wa);
    eb = __half22float2(*(const __half2*)&wb);
}

__global__ __launch_bounds__(BLOCK, 6)
void hash_encode_kernel(const float* __restrict__ inputs,
                        float4* __restrict__ out,
                        int npts)
{
    __shared__ float s_in[PTS_PER_BLK * 3];
    __shared__ float s_scale[NLEV];

    const int tid = threadIdx.x;
    {
        int gidx = blockIdx.x * (PTS_PER_BLK * 3) + tid;
        if (tid < PTS_PER_BLK * 3 && gidx < npts * 3)
            s_in[tid] = inputs[gidx];
        if (tid < NLEV)
            s_scale[tid] = g_scales[tid];
    }
    __syncthreads();

    const int p = tid >> 3;       // point within block (0..31)
    const int s = tid & 7;        // sub-thread: handles levels 2s, 2s+1
    const long long point = (long long)blockIdx.x * PTS_PER_BLK + p;
    if (point >= npts) return;

    const float x = s_in[p * 3 + 0];
    const float y = s_in[p * 3 + 1];
    const float z = s_in[p * 3 + 2];

    float4 r;

    #pragma unroll
    for (int i = 0; i < 2; ++i) {
        const int l = (s << 1) + i;
        const float scale  = s_scale[l];
        const uint32_t res = c_res[l];

        // pos = x*scale + 0.5, NO fma contraction (floor must match reference).
        const float posx = __fadd_rn(__fmul_rn(x, scale), 0.5f);
        const float posy = __fadd_rn(__fmul_rn(y, scale), 0.5f);
        const float posz = __fadd_rn(__fmul_rn(z, scale), 0.5f);
        const float fx = floorf(posx), fy = floorf(posy), fz = floorf(posz);
        const float tx = posx - fx,  ty = posy - fy,  tz = posz - fz;
        const uint32_t gx = (uint32_t)fx, gy = (uint32_t)fy, gz = (uint32_t)fz;
        const uint32_t rm1 = res - 1u;
        const uint32_t x0 = min(gx,      rm1), x1 = min(gx + 1u, rm1);
        const uint32_t y0 = min(gy,      rm1), y1 = min(gy + 1u, rm1);
        const uint32_t z0 = min(gz,      rm1), z1 = min(gz + 1u, rm1);

        const float wx0 = 1.0f - tx, wy0 = 1.0f - ty, wz0 = 1.0f - tz;
        float a0 = 0.0f, a1 = 0.0f;

        if (l >= 5) {
            const uint32_t* __restrict__ tabh = g_half + c_off[l];
            const uint32_t hy0 = y0 * 2654435761u, hy1 = y1 * 2654435761u;
            const uint32_t hz0 = z0 * 805459861u,  hz1 = z1 * 805459861u;
            const uint32_t m = 0x7FFFFu;
            uint32_t ia[4], ib[4];
            ia[0] = (x0 ^ hy0 ^ hz0) & m;  ib[0] = (x1 ^ hy0 ^ hz0) & m;
            ia[1] = (x0 ^ hy1 ^ hz0) & m;  ib[1] = (x1 ^ hy1 ^ hz0) & m;
            ia[2] = (x0 ^ hy0 ^ hz1) & m;  ib[2] = (x1 ^ hy0 ^ hz1) & m;
            ia[3] = (x0 ^ hy1 ^ hz1) & m;  ib[3] = (x1 ^ hy1 ^ hz1) & m;
            float2 ea[4], eb[4];
            #pragma unroll
            for (int q = 0; q < 4; ++q)
                pair_gather13(tabh, ia[q], ib[q], ea[q], eb[q]);
            #pragma unroll
            for (int q = 0; q < 4; ++q) {
                const float wy = (q & 1) ? ty : wy0;
                const float wz = (q & 2) ? tz : wz0;
                const float wyz = __fmul_rn(wy, wz);
                const float wa  = __fmul_rn(wx0, wyz);
                const float wb  = __fmul_rn(tx,  wyz);
                a0 = fmaf(wa, ea[q].x, a0);
                a1 = fmaf(wa, ea[q].y, a1);
                a0 = fmaf(wb, eb[q].x, a0);
                a1 = fmaf(wb, eb[q].y, a1);
            }
        } else {
            // Dense quad: one LDG.128 per z-plane; clamping baked at build.
            const uint4* __restrict__ quad = g_quad + c_off[l];
            const uint32_t r2 = res * res;
            const uint32_t base = x0 + y0 * res;
            const uint4 v0 = __ldg(quad + base + z0 * r2);
            const uint4 v1 = __ldg(quad + base + z1 * r2);
            const float2 e00a = __half22float2(*(const __half2*)&v0.x);
            const float2 e10a = __half22float2(*(const __half2*)&v0.y);
            const float2 e01a = __half22float2(*(const __half2*)&v0.z);
            const float2 e11a = __half22float2(*(const __half2*)&v0.w);
            const float2 e00b = __half22float2(*(const __half2*)&v1.x);
            const float2 e10b = __half22float2(*(const __half2*)&v1.y);
            const float2 e01b = __half22float2(*(const __half2*)&v1.z);
            const float2 e11b = __half22float2(*(const __half2*)&v1.w);
            const float w00a = __fmul_rn(__fmul_rn(wx0, wy0), wz0);
            const float w10a = __fmul_rn(__fmul_rn(tx,  wy0), wz0);
            const float w01a = __fmul_rn(__fmul_rn(wx0, ty),  wz0);
            const float w11a = __fmul_rn(__fmul_rn(tx,  ty),  wz0);
            const float w00b = __fmul_rn(__fmul_rn(wx0, wy0), tz);
            const float w10b = __fmul_rn(__fmul_rn(tx,  wy0), tz);
            const float w01b = __fmul_rn(__fmul_rn(wx0, ty),  tz);
            const float w11b = __fmul_rn(__fmul_rn(tx,  ty),  tz);
            a0 = fmaf(w00a, e00a.x, a0);  a1 = fmaf(w00a, e00a.y, a1);
            a0 = fmaf(w10a, e10a.x, a0);  a1 = fmaf(w10a, e10a.y, a1);
            a0 = fmaf(w01a, e01a.x, a0);  a1 = fmaf(w01a, e01a.y, a1);
            a0 = fmaf(w11a, e11a.x, a0);  a1 = fmaf(w11a, e11a.y, a1);
            a0 = fmaf(w00b, e00b.x, a0);  a1 = fmaf(w00b, e00b.y, a1);
            a0 = fmaf(w10b, e10b.x, a0);  a1 = fmaf(w10b, e10b.y, a1);
            a0 = fmaf(w01b, e01b.x, a0);  a1 = fmaf(w01b, e01b.y, a1);
            a0 = fmaf(w11b, e11b.x, a0);  a1 = fmaf(w11b, e11b.y, a1);
        }
        if (i == 0) { r.x = a0; r.y = a1; }
        else        { r.z = a0; r.w = a1; }
    }

    // Warp = 4 points x 8 subthreads -> 512B contiguous store, fully coalesced.
    out[point * 8 + s] = r;
}

extern "C" void kernel_launch(void* const* d_in, const int* in_sizes, int n_in,
                              void* d_out, int out_size)
{
    const float*  inputs = (const float*)d_in[0];
    const float2* emb    = (const float2*)d_in[1];
    float4*       out    = (float4*)d_out;

    const int npts = in_sizes[0] / 3;

    const int setup_n = (HASH_PARAMS / 2 > DENSE_PARAMS) ? HASH_PARAMS / 2
                                                         : DENSE_PARAMS;
    setup_kernel<<<(setup_n + 255) / 256, 256>>>(emb);

    const int total_threads = npts * 8;
    const int nblocks = (total_threads + BLOCK - 1) / BLOCK;
    hash_encode_kernel<<<nblocks, BLOCK>>>(inputs, out, npts);
}